// round 2
// baseline (speedup 1.0000x reference)
#include <cuda_runtime.h>
#include <cstdint>

typedef unsigned long long ull;

#define CH 16
#define FILT 32
#define TH 32
#define TW 64
#define SROWS 34      // TH + 2
#define SCOLS 66      // TW + 2
#define SIN_FLOATS (CH * SROWS * SCOLS)   // 35904
#define SW_FLOATS  (144 * FILT)           // 4608
#define SMEM_BYTES ((SIN_FLOATS + SW_FLOATS) * 4)

__device__ __forceinline__ ull fma2(ull a, ull b, ull c) {
    ull d;
    asm("fma.rn.f32x2 %0, %1, %2, %3;" : "=l"(d) : "l"(a), "l"(b), "l"(c));
    return d;
}

__device__ __forceinline__ ull pack2(float lo, float hi) {
    ull r;
    asm("mov.b64 %0, {%1, %2};" : "=l"(r) : "f"(lo), "f"(hi));
    return r;
}

__device__ __forceinline__ float sigmoidf_fast(float v) {
    return __fdividef(1.0f, 1.0f + __expf(-v));
}

__global__ __launch_bounds__(256, 1)
void conv_sig_kernel(const float* __restrict__ x,
                     const float* __restrict__ w,
                     const float* __restrict__ bias,
                     float* __restrict__ out) {
    extern __shared__ float smem[];
    float* s_in = smem;                 // [CH][SROWS][SCOLS]
    float* s_w  = smem + SIN_FLOATS;    // [144][32]

    const int tid  = threadIdx.x;
    const int x0   = blockIdx.x * TW;
    const int y0   = blockIdx.y * TH;
    const int b    = blockIdx.z;

    // ---- load weights (4608 floats) ----
    for (int i = tid; i < SW_FLOATS; i += 256) s_w[i] = w[i];

    // ---- load input tile with halo, zero-padded ----
    {
        const int warp = tid >> 5;
        const int lane = tid & 31;
        const int xbase = x0 - 1;
        for (int rowIdx = warp; rowIdx < CH * SROWS; rowIdx += 8) {
            const int c  = rowIdx / SROWS;
            const int r  = rowIdx - c * SROWS;
            const int gy = y0 - 1 + r;
            const bool yok = (gy >= 0) & (gy < 256);
            const float* src = x + (((b * CH + c) << 16) + (gy << 8)) + xbase;
            float* dst = s_in + rowIdx * SCOLS;
            #pragma unroll
            for (int k = 0; k < 3; ++k) {
                int xx = lane + 32 * k;
                if (xx < SCOLS) {
                    int gx = xbase + xx;
                    float v = 0.0f;
                    if (yok && gx >= 0 && gx < 256) v = src[xx];
                    dst[xx] = v;
                }
            }
        }
    }
    __syncthreads();

    const int tx8 = (tid & 7) * 8;   // x offset within tile (8 consecutive pixels)
    const int ty  = tid >> 3;        // row within tile (0..31)
    const int y   = y0 + ty;
    const int xo  = x0 + tx8;

    // 4 filter passes x (8 pixels x 8 filters as 4 f32x2 pairs)
    #pragma unroll 1
    for (int p = 0; p < 4; ++p) {
        const int fbase = p * 8;
        ull acc[8][4];
        #pragma unroll
        for (int px = 0; px < 8; ++px)
            #pragma unroll
            for (int j = 0; j < 4; ++j) acc[px][j] = 0ULL;

        #pragma unroll 1
        for (int c = 0; c < CH; ++c) {
            const float* sc = s_in + c * (SROWS * SCOLS);
            #pragma unroll
            for (int ky = 0; ky < 3; ++ky) {
                const float* srow = sc + (ty + ky) * SCOLS + tx8;
                float f[10];
                #pragma unroll
                for (int m = 0; m < 5; ++m) {
                    float2 v = *(const float2*)(srow + 2 * m);
                    f[2 * m]     = v.x;
                    f[2 * m + 1] = v.y;
                }
                ull dup[10];
                #pragma unroll
                for (int k = 0; k < 10; ++k) dup[k] = pack2(f[k], f[k]);

                const float* wr0 = s_w + (c * 9 + ky * 3) * FILT + fbase;
                #pragma unroll
                for (int kx = 0; kx < 3; ++kx) {
                    ull wp[4];
                    #pragma unroll
                    for (int j = 0; j < 4; ++j)
                        wp[j] = *(const ull*)(wr0 + kx * FILT + 2 * j);
                    #pragma unroll
                    for (int px = 0; px < 8; ++px) {
                        #pragma unroll
                        for (int j = 0; j < 4; ++j)
                            acc[px][j] = fma2(dup[px + kx], wp[j], acc[px][j]);
                    }
                }
            }
        }

        // epilogue: bias + sigmoid + store (float4 vectorized)
        #pragma unroll
        for (int j = 0; j < 4; ++j) {
            #pragma unroll
            for (int sub = 0; sub < 2; ++sub) {
                const int fIdx = fbase + 2 * j + sub;
                const int pix  = (y << 8) + xo;
                const float* bptr = bias + (fIdx << 16) + pix;
                float* optr = out + (((b * FILT + fIdx) << 16) + pix);

                float4 b0 = *(const float4*)(bptr);
                float4 b1 = *(const float4*)(bptr + 4);

                float v[8];
                #pragma unroll
                for (int px = 0; px < 8; ++px) {
                    float2 av = *(float2*)&acc[px][j];
                    v[px] = (sub == 0) ? av.x : av.y;
                }
                float4 o0, o1;
                o0.x = sigmoidf_fast(v[0] + b0.x);
                o0.y = sigmoidf_fast(v[1] + b0.y);
                o0.z = sigmoidf_fast(v[2] + b0.z);
                o0.w = sigmoidf_fast(v[3] + b0.w);
                o1.x = sigmoidf_fast(v[4] + b1.x);
                o1.y = sigmoidf_fast(v[5] + b1.y);
                o1.z = sigmoidf_fast(v[6] + b1.z);
                o1.w = sigmoidf_fast(v[7] + b1.w);
                *(float4*)(optr)     = o0;
                *(float4*)(optr + 4) = o1;
            }
        }
    }
}

extern "C" void kernel_launch(void* const* d_in, const int* in_sizes, int n_in,
                              void* d_out, int out_size) {
    const float* x    = (const float*)d_in[0];   // (16,16,256,256)
    const float* w    = (const float*)d_in[1];   // (144,32)
    const float* bias = (const float*)d_in[2];   // (32,256,256)
    float* out = (float*)d_out;                  // (16,32,256,256)

    cudaFuncSetAttribute(conv_sig_kernel,
                         cudaFuncAttributeMaxDynamicSharedMemorySize, SMEM_BYTES);

    dim3 grid(256 / TW, 256 / TH, 16);  // (4, 8, 16)
    conv_sig_kernel<<<grid, 256, SMEM_BYTES>>>(x, w, bias, out);
}

// round 5
// speedup vs baseline: 1.0012x; 1.0012x over previous
#include <cuda_runtime.h>
#include <cstdint>

typedef unsigned long long ull;

#define CH 16
#define FILT 32
#define TH 32
#define TW 64
#define SROWS 34      // TH + 2
#define SCOLS 66      // TW + 2
#define SIN_FLOATS (CH * SROWS * SCOLS)   // 35904
#define WD_PAIRS   (144 * FILT)           // 4608 dup'd weight pairs (ull each)
#define SMEM_BYTES (SIN_FLOATS * 4 + WD_PAIRS * 8)   // 143616 + 36864 = 180480

__device__ __forceinline__ ull fma2(ull a, ull b, ull c) {
    ull d;
    asm("fma.rn.f32x2 %0, %1, %2, %3;" : "=l"(d) : "l"(a), "l"(b), "l"(c));
    return d;
}

__device__ __forceinline__ ull pack2(float lo, float hi) {
    ull r;
    asm("mov.b64 %0, {%1, %2};" : "=l"(r) : "f"(lo), "f"(hi));
    return r;
}

__device__ __forceinline__ float sigmoidf_fast(float v) {
    return __fdividef(1.0f, 1.0f + __expf(-v));
}

__global__ __launch_bounds__(512, 1)
void conv_sig_kernel(const float* __restrict__ x,
                     const float* __restrict__ w,
                     const float* __restrict__ bias,
                     float* __restrict__ out) {
    extern __shared__ float smem[];
    float* s_in = smem;                                  // [CH][SROWS][SCOLS]
    ull*   s_wd = (ull*)(smem + SIN_FLOATS);             // [144][32] dup pairs

    const int tid  = threadIdx.x;
    const int x0   = blockIdx.x * TW;
    const int y0   = blockIdx.y * TH;
    const int b    = blockIdx.z;

    // ---- build duplicated weight table: s_wd[i] = {w[i], w[i]} ----
    for (int i = tid; i < WD_PAIRS; i += 512) {
        float v = w[i];
        s_wd[i] = pack2(v, v);
    }

    // ---- load input tile with halo, zero-padded ----
    {
        const int warp = tid >> 5;
        const int lane = tid & 31;
        const int xbase = x0 - 1;
        for (int rowIdx = warp; rowIdx < CH * SROWS; rowIdx += 16) {
            const int c  = rowIdx / SROWS;
            const int r  = rowIdx - c * SROWS;
            const int gy = y0 - 1 + r;
            const bool yok = (gy >= 0) & (gy < 256);
            const float* src = x + (((b * CH + c) << 16) + (gy << 8)) + xbase;
            float* dst = s_in + rowIdx * SCOLS;
            #pragma unroll
            for (int k = 0; k < 3; ++k) {
                int xx = lane + 32 * k;
                if (xx < SCOLS) {
                    int gx = xbase + xx;
                    float v = 0.0f;
                    if (yok && gx >= 0 && gx < 256) v = src[xx];
                    dst[xx] = v;
                }
            }
        }
    }
    __syncthreads();

    const int txg = tid & 7;
    const int ty  = (tid >> 3) & 31;
    const int fh  = tid >> 8;          // filter half (warp-uniform)
    const int tx8 = txg * 8;
    const int y   = y0 + ty;
    const int xo  = x0 + tx8;

    // 2 passes x (4 pixel-pairs x 8 filters)
    #pragma unroll 1
    for (int p = 0; p < 2; ++p) {
        const int fbase = fh * 16 + p * 8;
        ull acc[4][8];
        #pragma unroll
        for (int pp = 0; pp < 4; ++pp)
            #pragma unroll
            for (int f = 0; f < 8; ++f) acc[pp][f] = 0ULL;

        #pragma unroll 1
        for (int c = 0; c < CH; ++c) {
            const float* sc = s_in + c * (SROWS * SCOLS);
            #pragma unroll
            for (int ky = 0; ky < 3; ++ky) {
                const float* srow = sc + (ty + ky) * SCOLS + tx8;
                // aligned pixel pairs (f0,f1)(f2,f3)(f4,f5)(f6,f7)(f8,f9)
                ull u[5];
                #pragma unroll
                for (int m = 0; m < 5; ++m) u[m] = *(const ull*)(srow + 2 * m);
                float2 f2v[5];
                #pragma unroll
                for (int m = 0; m < 5; ++m) f2v[m] = *(float2*)&u[m];
                // shifted pairs for kx=1: (f1,f2)(f3,f4)(f5,f6)(f7,f8)
                ull sh[4];
                #pragma unroll
                for (int m = 0; m < 4; ++m) sh[m] = pack2(f2v[m].y, f2v[m + 1].x);

                const ull* wd = s_wd + (c * 9 + ky * 3) * FILT + fbase;
                #pragma unroll
                for (int kx = 0; kx < 3; ++kx) {
                    ull wp[8];
                    #pragma unroll
                    for (int f = 0; f < 8; ++f) wp[f] = wd[kx * FILT + f];
                    #pragma unroll
                    for (int f = 0; f < 8; ++f) {
                        #pragma unroll
                        for (int pp = 0; pp < 4; ++pp) {
                            ull pix = (kx == 0) ? u[pp] : (kx == 1) ? sh[pp] : u[pp + 1];
                            acc[pp][f] = fma2(pix, wp[f], acc[pp][f]);
                        }
                    }
                }
            }
        }

        // epilogue: bias + sigmoid + vectorized store
        const int pix = (y << 8) + xo;
        #pragma unroll
        for (int f = 0; f < 8; ++f) {
            const int fIdx = fbase + f;
            const float* bptr = bias + (fIdx << 16) + pix;
            float* optr = out + (((b * FILT + fIdx) << 16) + pix);

            float4 b0 = *(const float4*)(bptr);
            float4 b1 = *(const float4*)(bptr + 4);

            float2 a0 = *(float2*)&acc[0][f];
            float2 a1 = *(float2*)&acc[1][f];
            float2 a2 = *(float2*)&acc[2][f];
            float2 a3 = *(float2*)&acc[3][f];

            float4 o0, o1;
            o0.x = sigmoidf_fast(a0.x + b0.x);
            o0.y = sigmoidf_fast(a0.y + b0.y);
            o0.z = sigmoidf_fast(a1.x + b0.z);
            o0.w = sigmoidf_fast(a1.y + b0.w);
            o1.x = sigmoidf_fast(a2.x + b1.x);
            o1.y = sigmoidf_fast(a2.y + b1.y);
            o1.z = sigmoidf_fast(a3.x + b1.z);
            o1.w = sigmoidf_fast(a3.y + b1.w);
            *(float4*)(optr)     = o0;
            *(float4*)(optr + 4) = o1;
        }
    }
}

extern "C" void kernel_launch(void* const* d_in, const int* in_sizes, int n_in,
                              void* d_out, int out_size) {
    const float* x    = (const float*)d_in[0];   // (16,16,256,256)
    const float* w    = (const float*)d_in[1];   // (144,32)
    const float* bias = (const float*)d_in[2];   // (32,256,256)
    float* out = (float*)d_out;                  // (16,32,256,256)

    cudaFuncSetAttribute(conv_sig_kernel,
                         cudaFuncAttributeMaxDynamicSharedMemorySize, SMEM_BYTES);

    dim3 grid(256 / TW, 256 / TH, 16);  // (4, 8, 16)
    conv_sig_kernel<<<grid, 512, SMEM_BYTES>>>(x, w, bias, out);
}

// round 8
// speedup vs baseline: 2.1727x; 2.1701x over previous
#include <cuda_runtime.h>
#include <cuda_bf16.h>
#include <cstdint>

typedef uint32_t u32;

// ---- smem layout (bytes) ----
// A panels: ring of 4 input rows, each [128 px][64 k-slots] bf16 = 16 KB, hi and lo variants
#define SLOT_BYTES 16384
#define OFF_AHI 0
#define OFF_ALO (4 * SLOT_BYTES)               // 65536
#define OFF_B   (8 * SLOT_BYTES)               // 131072: [2 var][3 ky][32 f][64 k] bf16 = 24 KB
#define SMEM_TOTAL (OFF_B + 6 * 4096)          // 155648

#define SWZ(o) ((o) ^ (((o) >> 3) & 0x70))

__device__ __forceinline__ u32 smem_u32(const void* p) {
    u32 a;
    asm("{ .reg .u64 t; cvta.to.shared.u64 t, %1; cvt.u32.u64 %0, t; }" : "=r"(a) : "l"(p));
    return a;
}

__device__ __forceinline__ void ldsm_x4(u32* r, u32 addr) {
    asm volatile("ldmatrix.sync.aligned.m8n8.x4.shared.b16 {%0,%1,%2,%3}, [%4];"
                 : "=r"(r[0]), "=r"(r[1]), "=r"(r[2]), "=r"(r[3]) : "r"(addr));
}

__device__ __forceinline__ void mma16816(float* d, const u32* a, const u32* b) {
    asm volatile(
        "mma.sync.aligned.m16n8k16.row.col.f32.bf16.bf16.f32 "
        "{%0,%1,%2,%3}, {%4,%5,%6,%7}, {%8,%9}, {%0,%1,%2,%3};"
        : "+f"(d[0]), "+f"(d[1]), "+f"(d[2]), "+f"(d[3])
        : "r"(a[0]), "r"(a[1]), "r"(a[2]), "r"(a[3]), "r"(b[0]), "r"(b[1]));
}

// Build one input-row panel (hi + lo) into ring slot = (gy+1)&3.
// Panel: byte = px*128 + (c*4+kx)*2, SW128 swizzled; kx==3 slot zeroed.
__device__ __forceinline__ void build_panel(char* smem, const float* __restrict__ x,
                                            int b, int x0, int gy) {
    const int slot = (gy + 1) & 3;
    const u32 hiB = OFF_AHI + slot * SLOT_BYTES;
    const u32 loB = OFF_ALO + slot * SLOT_BYTES;
    const bool rowOK = (gy >= 0) && (gy < 256);
    const int gyc = rowOK ? gy : 0;
    const float* xrow = x + (((u32)b * 16) << 16) + (gyc << 8);
    const int tid = threadIdx.x;
    #pragma unroll
    for (int i = 0; i < 2; ++i) {
        const int task = tid + i * 512;      // 0..1023
        const int m    = task & 127;         // pixel within tile
        const int c0   = (task >> 7) * 2;    // channel pair base
        const int gx0  = x0 + m - 1;
        __align__(16) __nv_bfloat16 hi[8], lo[8];
        #pragma unroll
        for (int cc = 0; cc < 2; ++cc) {
            const float* src = xrow + (((u32)(c0 + cc)) << 16);
            #pragma unroll
            for (int kx = 0; kx < 3; ++kx) {
                const int gx = gx0 + kx;
                float v = 0.0f;
                if (rowOK && gx >= 0 && gx < 256) v = src[gx];
                __nv_bfloat16 h = __float2bfloat16(v);
                hi[cc * 4 + kx] = h;
                lo[cc * 4 + kx] = __float2bfloat16(v - __bfloat162float(h));
            }
            hi[cc * 4 + 3] = __float2bfloat16(0.0f);
            lo[cc * 4 + 3] = __float2bfloat16(0.0f);
        }
        const u32 off = SWZ((u32)(m * 128 + c0 * 8));
        *(uint4*)(smem + hiB + off) = *(const uint4*)hi;
        *(uint4*)(smem + loB + off) = *(const uint4*)lo;
    }
}

__global__ __launch_bounds__(512, 1)
void conv_mma_kernel(const float* __restrict__ x,
                     const float* __restrict__ w,
                     const float* __restrict__ bias,
                     float* __restrict__ out) {
    extern __shared__ char smem[];
    const u32 sb = smem_u32(smem);
    const int tid = threadIdx.x;
    const int wid = tid >> 5;
    const int lid = tid & 31;
    const int b  = blockIdx.z;
    const int x0 = blockIdx.x * 128;
    const int y0 = blockIdx.y * 16;

    // ---- Build B tiles: [var][ky][f row: 64 k-slots *2B], swizzled ----
    // k-slot = c*4+kx; kx==3 zero. W[k][f] with k = c*9+ky*3+kx.
    #pragma unroll
    for (int i = 0; i < 3; ++i) {
        const int wt = tid + i * 512;        // 0..1535
        const int f  = wt & 31;
        const int r  = wt >> 5;              // 0..47
        const int v  = r / 24;               // 0 = w_hi, 1 = w_lo
        const int rr = r - v * 24;
        const int ky = rr >> 3;
        const int c0 = (rr & 7) * 2;
        __align__(16) __nv_bfloat16 q[8];
        #pragma unroll
        for (int cc = 0; cc < 2; ++cc) {
            #pragma unroll
            for (int kx = 0; kx < 3; ++kx) {
                const float val = w[((c0 + cc) * 9 + ky * 3 + kx) * 32 + f];
                const __nv_bfloat16 h = __float2bfloat16(val);
                q[cc * 4 + kx] = (v == 0) ? h : __float2bfloat16(val - __bfloat162float(h));
            }
            q[cc * 4 + 3] = __float2bfloat16(0.0f);
        }
        const u32 off = SWZ((u32)(f * 128 + c0 * 8));
        *(uint4*)(smem + OFF_B + (v * 3 + ky) * 4096 + off) = *(const uint4*)q;
    }

    // ---- Prologue: panels for input rows y0-1 .. y0+2 ----
    build_panel(smem, x, b, x0, y0 - 1);
    build_panel(smem, x, b, x0, y0);
    build_panel(smem, x, b, x0, y0 + 1);
    build_panel(smem, x, b, x0, y0 + 2);

    // per-thread ldmatrix address components
    const int pxA   = (wid & 7) * 16 + (lid & 15);    // A: m0 + (l&15)
    const int cselA = (lid >> 1) & 8;                 // A: k0 + 0/8
    const int fB    = (lid & 7) + ((lid & 16) >> 1);  // B: f within 16-row group
    const int kselB = (lid & 8);                      // B: k0 + 0/8
    const int rowSel = wid >> 3;                      // 0/1: which output row of the pair
    const int m0     = (wid & 7) * 16;

    #pragma unroll 1
    for (int p = 0; p < 8; ++p) {
        __syncthreads();   // panels for this pair ready
        const int y = y0 + 2 * p + rowSel;

        float d[4][4];
        #pragma unroll
        for (int nt = 0; nt < 4; ++nt)
            #pragma unroll
            for (int j = 0; j < 4; ++j) d[nt][j] = 0.0f;

        #pragma unroll
        for (int ky = 0; ky < 3; ++ky) {
            const int slot = (y + ky) & 3;   // (gy+1)&3 with gy = y-1+ky
            const u32 aHiBase = sb + OFF_AHI + slot * SLOT_BYTES;
            const u32 aLoBase = sb + OFF_ALO + slot * SLOT_BYTES;
            const u32 bHiBase = sb + OFF_B + ky * 4096;
            const u32 bLoBase = bHiBase + 3 * 4096;
            #pragma unroll
            for (int kc = 0; kc < 4; ++kc) {
                const int k0 = kc * 16;
                const u32 aOff = SWZ((u32)(pxA * 128 + (k0 + cselA) * 2));
                u32 ah[4], al[4];
                ldsm_x4(ah, aHiBase + aOff);
                ldsm_x4(al, aLoBase + aOff);

                const u32 bOff0 = SWZ((u32)((fB)      * 128 + (k0 + kselB) * 2));
                const u32 bOff1 = SWZ((u32)((fB + 16) * 128 + (k0 + kselB) * 2));
                u32 bw[8], bl[8];
                ldsm_x4(bw,     bHiBase + bOff0);
                ldsm_x4(bw + 4, bHiBase + bOff1);
                ldsm_x4(bl,     bLoBase + bOff0);
                ldsm_x4(bl + 4, bLoBase + bOff1);

                #pragma unroll
                for (int nt = 0; nt < 4; ++nt) {
                    mma16816(d[nt], ah, bw + nt * 2);   // x_hi * w_hi
                    mma16816(d[nt], al, bw + nt * 2);   // x_lo * w_hi
                    mma16816(d[nt], ah, bl + nt * 2);   // x_hi * w_lo
                }
            }
        }

        // ---- epilogue: bias + sigmoid + store ----
        {
            const int r = lid >> 2;
            const int c = (lid & 3) * 2;
            const int xA = x0 + m0 + r;
            const int pixA = (y << 8) + xA;
            const int pixB = pixA + 8;
            #pragma unroll
            for (int nt = 0; nt < 4; ++nt) {
                #pragma unroll
                for (int j = 0; j < 4; ++j) {
                    const int f   = nt * 8 + c + (j & 1);
                    const int pix = (j & 2) ? pixB : pixA;
                    const float v = d[nt][j] + bias[(f << 16) + pix];
                    out[(((b << 5) + f) << 16) + pix] =
                        __fdividef(1.0f, 1.0f + __expf(-v));
                }
            }
        }

        __syncthreads();   // everyone done reading panels
        if (p < 7) {
            build_panel(smem, x, b, x0, y0 + 2 * p + 3);
            build_panel(smem, x, b, x0, y0 + 2 * p + 4);
        }
    }
}

extern "C" void kernel_launch(void* const* d_in, const int* in_sizes, int n_in,
                              void* d_out, int out_size) {
    const float* x    = (const float*)d_in[0];   // (16,16,256,256)
    const float* w    = (const float*)d_in[1];   // (144,32)
    const float* bias = (const float*)d_in[2];   // (32,256,256)
    float* out = (float*)d_out;                  // (16,32,256,256)

    cudaFuncSetAttribute(conv_mma_kernel,
                         cudaFuncAttributeMaxDynamicSharedMemorySize, SMEM_TOTAL);

    dim3 grid(2, 16, 16);   // x-tiles, y-tiles, batch
    conv_mma_kernel<<<grid, 512, SMEM_TOTAL>>>(x, w, bias, out);
}

// round 9
// speedup vs baseline: 2.3064x; 1.0616x over previous
#include <cuda_runtime.h>
#include <cuda_bf16.h>
#include <cstdint>

typedef uint32_t u32;

// ---- smem layout (bytes) ----
#define SLOT_BYTES 16384
#define OFF_AHI 0
#define OFF_ALO (4 * SLOT_BYTES)               // 65536
#define OFF_B   (8 * SLOT_BYTES)               // 131072: [2 var][3 ky][32 f][64 k] bf16
#define OFF_STAGE (OFF_B + 6 * 4096)           // 155648: raw x rows, 2 x 16c x 34 uint4
#define STAGE_ROW_BYTES 8704                   // 16*34*16
#define SMEM_TOTAL (OFF_STAGE + 2 * STAGE_ROW_BYTES)   // 173056

#define SWZ(o) ((o) ^ (((o) >> 3) & 0x70))

#define CP_COMMIT() asm volatile("cp.async.commit_group;" ::: "memory")
#define CP_WAIT0()  asm volatile("cp.async.wait_group 0;" ::: "memory")

__device__ __forceinline__ u32 smem_u32(const void* p) {
    u32 a;
    asm("{ .reg .u64 t; cvta.to.shared.u64 t, %1; cvt.u32.u64 %0, t; }" : "=r"(a) : "l"(p));
    return a;
}

__device__ __forceinline__ void cp_async16(u32 dst, const void* src, u32 bytes) {
    asm volatile("cp.async.ca.shared.global [%0], [%1], 16, %2;"
                 :: "r"(dst), "l"(src), "r"(bytes) : "memory");
}

__device__ __forceinline__ void ldsm_x4(u32* r, u32 addr) {
    asm volatile("ldmatrix.sync.aligned.m8n8.x4.shared.b16 {%0,%1,%2,%3}, [%4];"
                 : "=r"(r[0]), "=r"(r[1]), "=r"(r[2]), "=r"(r[3]) : "r"(addr));
}

__device__ __forceinline__ void mma16816(float* d, const u32* a, const u32* b) {
    asm volatile(
        "mma.sync.aligned.m16n8k16.row.col.f32.bf16.bf16.f32 "
        "{%0,%1,%2,%3}, {%4,%5,%6,%7}, {%8,%9}, {%0,%1,%2,%3};"
        : "+f"(d[0]), "+f"(d[1]), "+f"(d[2]), "+f"(d[3])
        : "r"(a[0]), "r"(a[1]), "r"(a[2]), "r"(a[3]), "r"(b[0]), "r"(b[1]));
}

// ---- stage one raw input row (16 ch x 136 px window) via cp.async ----
__device__ __forceinline__ void stage_row(u32 sb, const float* __restrict__ x,
                                          int b, int x0, int gy, int par) {
    const bool rowOK = (gy >= 0) && (gy < 256);
    const int gyc = rowOK ? gy : 0;
    const float* xrow = x + (((u32)b * 16) << 16) + (gyc << 8);
    const int tid = threadIdx.x;
    const u32 dbase = sb + OFF_STAGE + par * STAGE_ROW_BYTES;
    {
        const int g = tid;                 // 0..511
        const int c = g / 34, j = g - c * 34;
        const int px0 = x0 - 4 + 4 * j;
        const bool ok = rowOK && (px0 >= 0) && (px0 <= 252);
        const float* src = xrow + ((u32)c << 16) + (ok ? px0 : 0);
        cp_async16(dbase + g * 16, src, ok ? 16u : 0u);
    }
    if (tid < 32) {
        const int g = tid + 512;           // 512..543
        const int c = g / 34, j = g - c * 34;
        const int px0 = x0 - 4 + 4 * j;
        const bool ok = rowOK && (px0 >= 0) && (px0 <= 252);
        const float* src = xrow + ((u32)c << 16) + (ok ? px0 : 0);
        cp_async16(dbase + g * 16, src, ok ? 16u : 0u);
    }
}

// ---- build hi/lo panels for input row gy from staged floats ----
__device__ __forceinline__ void build_from_stage(char* smem, int gy, int par) {
    const int slot = (gy + 1) & 3;
    const u32 hiB = OFF_AHI + slot * SLOT_BYTES;
    const u32 loB = OFF_ALO + slot * SLOT_BYTES;
    const float* sv = (const float*)(smem + OFF_STAGE + par * STAGE_ROW_BYTES);
    const int tid = threadIdx.x;
    #pragma unroll
    for (int i = 0; i < 2; ++i) {
        const int task = tid + i * 512;      // 0..1023
        const int m    = task & 127;
        const int c0   = (task >> 7) * 2;
        __align__(16) __nv_bfloat16 hi[8], lo[8];
        #pragma unroll
        for (int cc = 0; cc < 2; ++cc) {
            const float* s = sv + (c0 + cc) * 136 + m + 3;
            #pragma unroll
            for (int kx = 0; kx < 3; ++kx) {
                const float v = s[kx];
                const __nv_bfloat16 h = __float2bfloat16(v);
                hi[cc * 4 + kx] = h;
                lo[cc * 4 + kx] = __float2bfloat16(v - __bfloat162float(h));
            }
            hi[cc * 4 + 3] = __float2bfloat16(0.0f);
            lo[cc * 4 + 3] = __float2bfloat16(0.0f);
        }
        const u32 off = SWZ((u32)(m * 128 + c0 * 8));
        *(uint4*)(smem + hiB + off) = *(const uint4*)hi;
        *(uint4*)(smem + loB + off) = *(const uint4*)lo;
    }
}

__global__ __launch_bounds__(512, 1)
void conv_mma_kernel(const float* __restrict__ x,
                     const float* __restrict__ w,
                     const float* __restrict__ bias,
                     float* __restrict__ out) {
    extern __shared__ char smem[];
    const u32 sb = smem_u32(smem);
    const int tid = threadIdx.x;
    const int wid = tid >> 5;
    const int lid = tid & 31;
    const int b  = blockIdx.z;
    const int x0 = blockIdx.x * 128;
    const int y0 = blockIdx.y * 16;

    // Stage first input-row pair while we build B tiles
    stage_row(sb, x, b, x0, y0 - 1, 0);
    stage_row(sb, x, b, x0, y0,     1);
    CP_COMMIT();

    // ---- Build B tiles: [var][ky][f row: 64 k-slots *2B], swizzled ----
    #pragma unroll
    for (int i = 0; i < 3; ++i) {
        const int wt = tid + i * 512;        // 0..1535
        const int f  = wt & 31;
        const int r  = wt >> 5;              // 0..47
        const int v  = r / 24;               // 0 = w_hi, 1 = w_lo
        const int rr = r - v * 24;
        const int ky = rr >> 3;
        const int c0 = (rr & 7) * 2;
        __align__(16) __nv_bfloat16 q[8];
        #pragma unroll
        for (int cc = 0; cc < 2; ++cc) {
            #pragma unroll
            for (int kx = 0; kx < 3; ++kx) {
                const float val = w[((c0 + cc) * 9 + ky * 3 + kx) * 32 + f];
                const __nv_bfloat16 h = __float2bfloat16(val);
                q[cc * 4 + kx] = (v == 0) ? h : __float2bfloat16(val - __bfloat162float(h));
            }
            q[cc * 4 + 3] = __float2bfloat16(0.0f);
        }
        const u32 off = SWZ((u32)(f * 128 + c0 * 8));
        *(uint4*)(smem + OFF_B + (v * 3 + ky) * 4096 + off) = *(const uint4*)q;
    }

    // ---- Prologue: build panels for input rows y0-1 .. y0+2 ----
    CP_WAIT0();
    __syncthreads();
    build_from_stage(smem, y0 - 1, 0);
    build_from_stage(smem, y0,     1);
    stage_row(sb, x, b, x0, y0 + 1, 0);
    stage_row(sb, x, b, x0, y0 + 2, 1);
    CP_COMMIT();
    CP_WAIT0();
    __syncthreads();
    build_from_stage(smem, y0 + 1, 0);
    build_from_stage(smem, y0 + 2, 1);

    // per-thread ldmatrix address components
    const int pxA   = (wid & 7) * 16 + (lid & 15);
    const int cselA = (lid >> 1) & 8;
    const int fB    = (lid & 7) + ((lid & 16) >> 1);
    const int kselB = (lid & 8);
    const int rowSel = wid >> 3;
    const int m0     = (wid & 7) * 16;

    #pragma unroll 1
    for (int p = 0; p < 8; ++p) {
        __syncthreads();   // panels for this pair visible
        // kick off staging of the NEXT pair's raw rows (latency hides under MMA)
        if (p < 7) {
            stage_row(sb, x, b, x0, y0 + 2 * p + 3, 0);
            stage_row(sb, x, b, x0, y0 + 2 * p + 4, 1);
            CP_COMMIT();
        }

        const int y = y0 + 2 * p + rowSel;

        float d[4][4];
        #pragma unroll
        for (int nt = 0; nt < 4; ++nt)
            #pragma unroll
            for (int j = 0; j < 4; ++j) d[nt][j] = 0.0f;

        #pragma unroll
        for (int ky = 0; ky < 3; ++ky) {
            const int slot = (y + ky) & 3;
            const u32 aHiBase = sb + OFF_AHI + slot * SLOT_BYTES;
            const u32 aLoBase = sb + OFF_ALO + slot * SLOT_BYTES;
            const u32 bHiBase = sb + OFF_B + ky * 4096;
            const u32 bLoBase = bHiBase + 3 * 4096;
            #pragma unroll
            for (int kc = 0; kc < 4; ++kc) {
                const int k0 = kc * 16;
                const u32 aOff = SWZ((u32)(pxA * 128 + (k0 + cselA) * 2));
                u32 ah[4], al[4];
                ldsm_x4(ah, aHiBase + aOff);
                ldsm_x4(al, aLoBase + aOff);

                const u32 bOff0 = SWZ((u32)((fB)      * 128 + (k0 + kselB) * 2));
                const u32 bOff1 = SWZ((u32)((fB + 16) * 128 + (k0 + kselB) * 2));
                u32 bw[8], bl[8];
                ldsm_x4(bw,     bHiBase + bOff0);
                ldsm_x4(bw + 4, bHiBase + bOff1);
                ldsm_x4(bl,     bLoBase + bOff0);
                ldsm_x4(bl + 4, bLoBase + bOff1);

                #pragma unroll
                for (int nt = 0; nt < 4; ++nt) {
                    mma16816(d[nt], ah, bw + nt * 2);   // x_hi * w_hi
                    mma16816(d[nt], al, bw + nt * 2);   // x_lo * w_hi
                    mma16816(d[nt], ah, bl + nt * 2);   // x_hi * w_lo
                }
            }
        }

        // ---- epilogue: bias + sigmoid + store ----
        {
            const int r = lid >> 2;
            const int c = (lid & 3) * 2;
            const int xA = x0 + m0 + r;
            const int pixA = (y << 8) + xA;
            const int pixB = pixA + 8;
            #pragma unroll
            for (int nt = 0; nt < 4; ++nt) {
                #pragma unroll
                for (int j = 0; j < 4; ++j) {
                    const int f   = nt * 8 + c + (j & 1);
                    const int pix = (j & 2) ? pixB : pixA;
                    const float v = d[nt][j] + bias[(f << 16) + pix];
                    out[(((b << 5) + f) << 16) + pix] =
                        __fdividef(1.0f, 1.0f + __expf(-v));
                }
            }
        }

        if (p < 7) {
            CP_WAIT0();
            __syncthreads();   // all warps done reading old panels + staging ready
            build_from_stage(smem, y0 + 2 * p + 3, 0);
            build_from_stage(smem, y0 + 2 * p + 4, 1);
        }
    }
}

extern "C" void kernel_launch(void* const* d_in, const int* in_sizes, int n_in,
                              void* d_out, int out_size) {
    const float* x    = (const float*)d_in[0];   // (16,16,256,256)
    const float* w    = (const float*)d_in[1];   // (144,32)
    const float* bias = (const float*)d_in[2];   // (32,256,256)
    float* out = (float*)d_out;                  // (16,32,256,256)

    cudaFuncSetAttribute(conv_mma_kernel,
                         cudaFuncAttributeMaxDynamicSharedMemorySize, SMEM_TOTAL);

    dim3 grid(2, 16, 16);   // x-tiles, y-tiles, batch
    conv_mma_kernel<<<grid, 512, SMEM_TOTAL>>>(x, w, bias, out);
}

// round 10
// speedup vs baseline: 2.8374x; 1.2302x over previous
#include <cuda_runtime.h>
#include <cuda_bf16.h>
#include <cstdint>

typedef uint32_t u32;

// ---- smem layout (bytes) ----
#define PANEL_BYTES 4224                        // 132 rows x 32B (16ch bf16)
#define OFF_AHI 0                               // ring of 4 input rows (hi)
#define OFF_ALO (4 * PANEL_BYTES)               // 16896 (lo ring)
#define OFF_B   (8 * PANEL_BYTES)               // 33792: [2 var][9 pos][32 f][32B]
#define B_TILE  1024
#define OFF_STAGE (OFF_B + 18 * B_TILE)         // 52224
#define STAGE_ROW_BYTES 8704                    // 16 ch x 34 x 16B
#define SMEM_TOTAL (OFF_STAGE + 2 * STAGE_ROW_BYTES)   // 69632

// row/half -> swizzled byte offset inside a 32B-row panel (conflict-free LDSM)
#define ADDRSWZ(r, half16) ((((u32)(r) << 5) + (half16)) ^ (((r) & 4) << 2))

#define CP_COMMIT() asm volatile("cp.async.commit_group;" ::: "memory")
#define CP_WAIT0()  asm volatile("cp.async.wait_group 0;" ::: "memory")

__device__ __forceinline__ u32 smem_u32(const void* p) {
    u32 a;
    asm("{ .reg .u64 t; cvta.to.shared.u64 t, %1; cvt.u32.u64 %0, t; }" : "=r"(a) : "l"(p));
    return a;
}

__device__ __forceinline__ void cp_async16(u32 dst, const void* src, u32 bytes) {
    asm volatile("cp.async.ca.shared.global [%0], [%1], 16, %2;"
                 :: "r"(dst), "l"(src), "r"(bytes) : "memory");
}

__device__ __forceinline__ void ldsm_x4(u32* r, u32 addr) {
    asm volatile("ldmatrix.sync.aligned.m8n8.x4.shared.b16 {%0,%1,%2,%3}, [%4];"
                 : "=r"(r[0]), "=r"(r[1]), "=r"(r[2]), "=r"(r[3]) : "r"(addr));
}

__device__ __forceinline__ void mma16816(float* d, const u32* a, const u32* b) {
    asm volatile(
        "mma.sync.aligned.m16n8k16.row.col.f32.bf16.bf16.f32 "
        "{%0,%1,%2,%3}, {%4,%5,%6,%7}, {%8,%9}, {%0,%1,%2,%3};"
        : "+f"(d[0]), "+f"(d[1]), "+f"(d[2]), "+f"(d[3])
        : "r"(a[0]), "r"(a[1]), "r"(a[2]), "r"(a[3]), "r"(b[0]), "r"(b[1]));
}

// ---- stage one raw input row (16 ch x 136 px window) via cp.async ----
__device__ __forceinline__ void stage_row(u32 sb, const float* __restrict__ x,
                                          int b, int x0, int gy, int par) {
    const bool rowOK = (gy >= 0) && (gy < 256);
    const int gyc = rowOK ? gy : 0;
    const float* xrow = x + (((u32)b * 16) << 16) + (gyc << 8);
    const int tid = threadIdx.x;
    const u32 dbase = sb + OFF_STAGE + par * STAGE_ROW_BYTES;
    {
        const int g = tid;                 // 0..511
        const int c = g / 34, j = g - c * 34;
        const int px0 = x0 - 4 + 4 * j;
        const bool ok = rowOK && (px0 >= 0) && (px0 <= 252);
        const float* src = xrow + ((u32)c << 16) + (ok ? px0 : 0);
        cp_async16(dbase + g * 16, src, ok ? 16u : 0u);
    }
    if (tid < 32) {
        const int g = tid + 512;           // 512..543
        const int c = g / 34, j = g - c * 34;
        const int px0 = x0 - 4 + 4 * j;
        const bool ok = rowOK && (px0 >= 0) && (px0 <= 252);
        const float* src = xrow + ((u32)c << 16) + (ok ? px0 : 0);
        cp_async16(dbase + g * 16, src, ok ? 16u : 0u);
    }
}

// ---- build hi/lo panels for two staged input rows ----
// Panel row r (0..129) <-> gx = x0-1+r ; 16 channels, one conversion per value.
__device__ __forceinline__ void build_pair(char* smem, int gy0, int gy1) {
    const int tid = threadIdx.x;
    const int which = tid >> 8;          // 0 or 1
    const int r = tid & 255;
    if (r < 130) {
        const int gy = which ? gy1 : gy0;
        const int slot = (gy + 1) & 3;
        const float* sv = (const float*)(smem + OFF_STAGE + which * STAGE_ROW_BYTES);
        __align__(16) __nv_bfloat16 hi[16], lo[16];
        #pragma unroll
        for (int c = 0; c < 16; ++c) {
            const float v = sv[c * 136 + r + 3];
            const __nv_bfloat16 h = __float2bfloat16(v);
            hi[c] = h;
            lo[c] = __float2bfloat16(v - __bfloat162float(h));
        }
        char* hp = smem + OFF_AHI + slot * PANEL_BYTES;
        char* lp = smem + OFF_ALO + slot * PANEL_BYTES;
        const u32 o0 = ADDRSWZ(r, 0);
        const u32 o1 = ADDRSWZ(r, 16);
        *(uint4*)(hp + o0) = *(const uint4*)hi;
        *(uint4*)(hp + o1) = *(const uint4*)(hi + 8);
        *(uint4*)(lp + o0) = *(const uint4*)lo;
        *(uint4*)(lp + o1) = *(const uint4*)(lo + 8);
    }
}

__global__ __launch_bounds__(512, 1)
void conv_mma_kernel(const float* __restrict__ x,
                     const float* __restrict__ w,
                     const float* __restrict__ bias,
                     float* __restrict__ out) {
    extern __shared__ char smem[];
    const u32 sb = smem_u32(smem);
    const int tid = threadIdx.x;
    const int wid = tid >> 5;
    const int lid = tid & 31;
    const int b  = blockIdx.z;
    const int x0 = blockIdx.x * 128;
    const int y0 = blockIdx.y * 16;

    // Stage first input-row pair while we build B tiles
    stage_row(sb, x, b, x0, y0 - 1, 0);
    stage_row(sb, x, b, x0, y0,     1);
    CP_COMMIT();

    // ---- Build B tiles: [var][pos = ky*3+kx][f row: 16 ch x 2B], swizzled ----
    #pragma unroll
    for (int i = 0; i < 2; ++i) {
        const int t = tid + i * 512;         // 0..1023, use < 576
        if (t < 576) {
            const int var = t / 288;          // 0 = w_hi, 1 = w_lo
            const int rem = t - var * 288;
            const int pos = rem >> 5;         // 0..8 (= ky*3+kx)
            const int f   = rem & 31;
            __align__(16) __nv_bfloat16 q[16];
            #pragma unroll
            for (int c = 0; c < 16; ++c) {
                const float val = w[(c * 9 + pos) * 32 + f];
                const __nv_bfloat16 h = __float2bfloat16(val);
                q[c] = (var == 0) ? h : __float2bfloat16(val - __bfloat162float(h));
            }
            char* bp = smem + OFF_B + (var * 9 + pos) * B_TILE;
            *(uint4*)(bp + ADDRSWZ(f, 0))  = *(const uint4*)q;
            *(uint4*)(bp + ADDRSWZ(f, 16)) = *(const uint4*)(q + 8);
        }
    }

    // ---- Prologue: build panels for input rows y0-1 .. y0+2 ----
    CP_WAIT0();
    __syncthreads();
    build_pair(smem, y0 - 1, y0);
    stage_row(sb, x, b, x0, y0 + 1, 0);
    stage_row(sb, x, b, x0, y0 + 2, 1);
    CP_COMMIT();
    CP_WAIT0();
    __syncthreads();
    build_pair(smem, y0 + 1, y0 + 2);

    // per-thread fragment address components (loop-invariant)
    const int rowSel = wid >> 3;
    const int m0     = (wid & 7) * 16;
    const int pxA    = m0 + (lid & 15);
    const u32 halfA  = (u32)((lid >> 4) << 4);
    u32 aRel[3];
    #pragma unroll
    for (int kx = 0; kx < 3; ++kx) aRel[kx] = ADDRSWZ(pxA + kx, halfA);
    const int f0 = (lid & 7) + ((lid & 16) >> 1);
    const u32 bRel = ADDRSWZ(f0, (u32)((lid & 8) << 1));

    #pragma unroll 1
    for (int p = 0; p < 8; ++p) {
        __syncthreads();   // panels for this pair visible
        if (p < 7) {       // stage next pair, hides under MMA
            stage_row(sb, x, b, x0, y0 + 2 * p + 3, 0);
            stage_row(sb, x, b, x0, y0 + 2 * p + 4, 1);
            CP_COMMIT();
        }

        const int y = y0 + 2 * p + rowSel;

        float d[4][4];
        #pragma unroll
        for (int nt = 0; nt < 4; ++nt)
            #pragma unroll
            for (int j = 0; j < 4; ++j) d[nt][j] = 0.0f;

        #pragma unroll
        for (int ky = 0; ky < 3; ++ky) {
            const u32 aHiBase = sb + OFF_AHI + (u32)(((y + ky) & 3) * PANEL_BYTES);
            const u32 aLoBase = aHiBase + OFF_ALO;
            #pragma unroll
            for (int kx = 0; kx < 3; ++kx) {
                u32 ah[4], al[4];
                ldsm_x4(ah, aHiBase + aRel[kx]);
                ldsm_x4(al, aLoBase + aRel[kx]);

                const u32 bHi = sb + OFF_B + (u32)((ky * 3 + kx) * B_TILE);
                const u32 bLo = bHi + 9 * B_TILE;
                u32 bw[8], bl[8];
                ldsm_x4(bw,     bHi + bRel);
                ldsm_x4(bw + 4, bHi + bRel + 512);
                ldsm_x4(bl,     bLo + bRel);
                ldsm_x4(bl + 4, bLo + bRel + 512);

                #pragma unroll
                for (int nt = 0; nt < 4; ++nt) {
                    mma16816(d[nt], ah, bw + nt * 2);   // x_hi * w_hi
                    mma16816(d[nt], al, bw + nt * 2);   // x_lo * w_hi
                    mma16816(d[nt], ah, bl + nt * 2);   // x_hi * w_lo
                }
            }
        }

        // ---- epilogue: bias + sigmoid + store ----
        {
            const int r = lid >> 2;
            const int c = (lid & 3) * 2;
            const int xA = x0 + m0 + r;
            const int pixA = (y << 8) + xA;
            const int pixB = pixA + 8;
            #pragma unroll
            for (int nt = 0; nt < 4; ++nt) {
                #pragma unroll
                for (int j = 0; j < 4; ++j) {
                    const int f   = nt * 8 + c + (j & 1);
                    const int pix = (j & 2) ? pixB : pixA;
                    const float v = d[nt][j] + bias[(f << 16) + pix];
                    out[(((b << 5) + f) << 16) + pix] =
                        __fdividef(1.0f, 1.0f + __expf(-v));
                }
            }
        }

        if (p < 7) {
            CP_WAIT0();
            __syncthreads();   // all warps done with old panels + staging landed
            build_pair(smem, y0 + 2 * p + 3, y0 + 2 * p + 4);
        }
    }
}

extern "C" void kernel_launch(void* const* d_in, const int* in_sizes, int n_in,
                              void* d_out, int out_size) {
    const float* x    = (const float*)d_in[0];   // (16,16,256,256)
    const float* w    = (const float*)d_in[1];   // (144,32)
    const float* bias = (const float*)d_in[2];   // (32,256,256)
    float* out = (float*)d_out;                  // (16,32,256,256)

    cudaFuncSetAttribute(conv_mma_kernel,
                         cudaFuncAttributeMaxDynamicSharedMemorySize, SMEM_TOTAL);

    dim3 grid(2, 16, 16);   // x-tiles, y-tiles, batch
    conv_mma_kernel<<<grid, 512, SMEM_TOTAL>>>(x, w, bias, out);
}